// round 6
// baseline (speedup 1.0000x reference)
#include <cuda_runtime.h>
#include <cuda_fp16.h>

#define N_NODES 100000
#define N_EDGES 1600000
#define IN_DIM  128
#define HID     64
#define N_GRAPHS 64

#define SCAN_B 1024
#define SCAN_NB ((N_NODES + SCAN_B - 1) / SCAN_B)   // 98

// ---------------- static device scratch (no allocations allowed) ----------------
__device__ int   g_cnt[N_NODES];          // in-degree (excluding self-loop)
__device__ int   g_cur[N_NODES];          // scatter cursors
__device__ int   g_off[N_NODES + 1];      // CSR offsets by dst
__device__ float g_dis[N_NODES];          // deg^{-1/2}
__device__ int   g_bsum[SCAN_NB];         // per-block sums
__device__ int   g_bpre[SCAN_NB];         // exclusive-scanned block sums
__device__ __align__(16) int2  g_csr[N_EDGES];      // (src, norm-bits) packed
__device__ __align__(16) __half g_Ah[(size_t)N_NODES * HID];  // GEMM out, fp16 messages
__device__ __align__(16) float g_B[(size_t)N_NODES * HID];    // layer output fp32
__device__ float g_pooled[N_GRAPHS * HID];

// ---------------- preprocessing ----------------
__global__ __launch_bounds__(256) void k_zero() {
    int i = blockIdx.x * blockDim.x + threadIdx.x;
    if (i < N_NODES) { g_cnt[i] = 0; g_cur[i] = 0; }
}

__global__ __launch_bounds__(256) void k_count(const int* __restrict__ dst32) {
    int e = blockIdx.x * blockDim.x + threadIdx.x;
    if (e < N_EDGES) atomicAdd(&g_cnt[dst32[e]], 1);
}

// ---- scan stage 1: coalesced per-block sums, fused with dis = rsqrt(cnt+1) ----
__global__ __launch_bounds__(SCAN_B) void k_scan1() {
    int i = blockIdx.x * SCAN_B + threadIdx.x;
    int v = 0;
    if (i < N_NODES) {
        v = g_cnt[i];
        g_dis[i] = rsqrtf((float)(v + 1));   // +1 self-loop
    }
    int lane = threadIdx.x & 31, wid = threadIdx.x >> 5;
    int s = v;
#pragma unroll
    for (int d = 16; d > 0; d >>= 1) s += __shfl_down_sync(~0u, s, d);
    __shared__ int wsum[32];
    if (lane == 0) wsum[wid] = s;
    __syncthreads();
    if (wid == 0) {
        int t = wsum[lane];
#pragma unroll
        for (int d = 16; d > 0; d >>= 1) t += __shfl_down_sync(~0u, t, d);
        if (lane == 0) g_bsum[blockIdx.x] = t;
    }
}

// ---- scan stage 2: scan the 98 block sums (1 tiny block) ----
__global__ __launch_bounds__(128) void k_scan2() {
    __shared__ int sm[128];
    int t = threadIdx.x;
    int v = (t < SCAN_NB) ? g_bsum[t] : 0;
    sm[t] = v;
    __syncthreads();
    for (int d = 1; d < 128; d <<= 1) {
        int y = (t >= d) ? sm[t - d] : 0;
        __syncthreads();
        sm[t] += y;
        __syncthreads();
    }
    if (t < SCAN_NB) g_bpre[t] = sm[t] - v;     // exclusive
    if (t == 0) g_off[N_NODES] = N_EDGES;
}

// ---- scan stage 3: block-wide exclusive scan + block prefix, coalesced ----
__global__ __launch_bounds__(SCAN_B) void k_scan3() {
    int i = blockIdx.x * SCAN_B + threadIdx.x;
    int v = (i < N_NODES) ? g_cnt[i] : 0;
    int lane = threadIdx.x & 31, wid = threadIdx.x >> 5;
    int x = v;
#pragma unroll
    for (int d = 1; d < 32; d <<= 1) {
        int y = __shfl_up_sync(~0u, x, d);
        if (lane >= d) x += y;
    }
    __shared__ int wsum[32];
    if (lane == 31) wsum[wid] = x;
    __syncthreads();
    if (wid == 0) {
        int s = wsum[lane];
#pragma unroll
        for (int d = 1; d < 32; d <<= 1) {
            int y = __shfl_up_sync(~0u, s, d);
            if (lane >= d) s += y;
        }
        wsum[lane] = s;
    }
    __syncthreads();
    if (i < N_NODES)
        g_off[i] = (x - v) + (wid > 0 ? wsum[wid - 1] : 0) + g_bpre[blockIdx.x];
}

__global__ __launch_bounds__(256) void k_scatter(const int* __restrict__ ei) {
    int e = blockIdx.x * blockDim.x + threadIdx.x;
    if (e >= N_EDGES) return;
    int s = ei[e];
    int d = ei[N_EDGES + e];
    int pos = g_off[d] + atomicAdd(&g_cur[d], 1);
    float nrm = g_dis[s] * g_dis[d];
    g_csr[pos] = make_int2(s, __float_as_int(nrm));
}

// ---------------- GEMM: Ah = act(X) @ W  (fp32 compute, fp16 output) ----------------
#define GEMM_T 128
template<int K, bool RELU, bool FROM_B>
__global__ __launch_bounds__(GEMM_T) void k_gemm(const float* __restrict__ Xext,
                                                 const float* __restrict__ W) {
    __shared__ float Wsh[K * HID];
    for (int i = threadIdx.x; i < K * HID; i += blockDim.x) Wsh[i] = W[i];
    __syncthreads();

    int row = blockIdx.x * blockDim.x + threadIdx.x;
    if (row >= N_NODES) return;

    const float* X = FROM_B ? g_B : Xext;
    const float4* xr = (const float4*)(X + (size_t)row * K);

    float acc[HID];
#pragma unroll
    for (int c = 0; c < HID; c++) acc[c] = 0.0f;

#pragma unroll 2
    for (int k4 = 0; k4 < K / 4; k4++) {
        float4 xv = xr[k4];
        if (RELU) {
            xv.x = fmaxf(xv.x, 0.0f); xv.y = fmaxf(xv.y, 0.0f);
            xv.z = fmaxf(xv.z, 0.0f); xv.w = fmaxf(xv.w, 0.0f);
        }
        float xk_arr[4] = {xv.x, xv.y, xv.z, xv.w};
#pragma unroll
        for (int kk = 0; kk < 4; kk++) {
            float xk = xk_arr[kk];
            const float4* wr = (const float4*)(Wsh + (k4 * 4 + kk) * HID);
#pragma unroll
            for (int c4 = 0; c4 < 16; c4++) {
                float4 w = wr[c4];
                acc[4 * c4 + 0] += xk * w.x;
                acc[4 * c4 + 1] += xk * w.y;
                acc[4 * c4 + 2] += xk * w.z;
                acc[4 * c4 + 3] += xk * w.w;
            }
        }
    }

    // pack 64 fp32 -> 64 fp16, 8x STG.128
    uint4* o = (uint4*)(g_Ah + (size_t)row * HID);
#pragma unroll
    for (int q = 0; q < 8; q++) {
        uint4 pk;
        __half2 h0 = __floats2half2_rn(acc[8 * q + 0], acc[8 * q + 1]);
        __half2 h1 = __floats2half2_rn(acc[8 * q + 2], acc[8 * q + 3]);
        __half2 h2 = __floats2half2_rn(acc[8 * q + 4], acc[8 * q + 5]);
        __half2 h3 = __floats2half2_rn(acc[8 * q + 6], acc[8 * q + 7]);
        pk.x = *(unsigned int*)&h0;
        pk.y = *(unsigned int*)&h1;
        pk.z = *(unsigned int*)&h2;
        pk.w = *(unsigned int*)&h3;
        o[q] = pk;
    }
}

// ---------------- aggregation: one warp per dst node ----------------
// B[d,:] = Ah[d,:]*dis[d]^2 + b + sum_{e in CSR[d]} Ah[src_e,:]*norm_e
// Each lane handles 2 columns via one half2 (4B) -> warp reads 128B/edge = 1 L2 line.
__global__ __launch_bounds__(256) void k_agg(const float* __restrict__ bias) {
    int w = (blockIdx.x * blockDim.x + threadIdx.x) >> 5;
    if (w >= N_NODES) return;
    int lane = threadIdx.x & 31;

    const __half2* A2 = (const __half2*)g_Ah;
    float dis = g_dis[w];
    float2 b2 = ((const float2*)bias)[lane];
    float2 self = __half22float2(A2[(size_t)w * 32 + lane]);
    float sn = dis * dis;
    float ax = self.x * sn + b2.x;
    float ay = self.y * sn + b2.y;

    int p   = g_off[w];
    int end = g_off[w + 1];
    for (; p + 2 <= end; p += 2) {
        int2 e0 = g_csr[p];
        int2 e1 = g_csr[p + 1];
        float n0 = __int_as_float(e0.y);
        float n1 = __int_as_float(e1.y);
        float2 v0 = __half22float2(A2[(size_t)e0.x * 32 + lane]);
        float2 v1 = __half22float2(A2[(size_t)e1.x * 32 + lane]);
        ax += v0.x * n0; ay += v0.y * n0;
        ax += v1.x * n1; ay += v1.y * n1;
    }
    if (p < end) {
        int2 e0 = g_csr[p];
        float n0 = __int_as_float(e0.y);
        float2 v0 = __half22float2(A2[(size_t)e0.x * 32 + lane]);
        ax += v0.x * n0; ay += v0.y * n0;
    }

    ((float2*)g_B)[(size_t)w * 32 + lane] = make_float2(ax, ay);
}

// ---------------- global mean pool (batch is sorted int32) ----------------
__device__ __forceinline__ int lb_i32(const int* a, int n, int v) {
    int lo = 0, hi = n;
    while (lo < hi) {
        int mid = (lo + hi) >> 1;
        if (a[mid] < v) lo = mid + 1; else hi = mid;
    }
    return lo;
}

__global__ __launch_bounds__(256) void k_pool(const int* __restrict__ batch) {
    int g = blockIdx.x;                 // one block per graph
    int lo = lb_i32(batch, N_NODES, g);
    int hi = lb_i32(batch, N_NODES, g + 1);
    int c = threadIdx.x & 63;
    int sub = threadIdx.x >> 6;         // 0..3
    float s = 0.0f;
    for (int i = lo + sub; i < hi; i += 4)
        s += g_B[(size_t)i * HID + c];
    __shared__ float red[256];
    red[threadIdx.x] = s;
    __syncthreads();
    if (sub == 0) {
        float tot = red[c] + red[64 + c] + red[128 + c] + red[192 + c];
        float cnt = (float)(hi - lo);
        g_pooled[g * HID + c] = tot / fmaxf(cnt, 1.0f);
    }
}

// ---------------- classifier MLP: [64,64] -> relu[64,32] -> [64,2] ----------------
__global__ __launch_bounds__(64) void k_cls(const float* __restrict__ Wc1,
                                            const float* __restrict__ bc1,
                                            const float* __restrict__ Wc2,
                                            const float* __restrict__ bc2,
                                            float* __restrict__ out) {
    __shared__ float W1s[64 * 32];
    __shared__ float W2s[32 * 2];
    int t = threadIdx.x;  // 64 threads, one per graph
    for (int i = t; i < 64 * 32; i += 64) W1s[i] = Wc1[i];
    if (t < 64) W2s[t] = Wc2[t];
    __syncthreads();

    float p[64];
#pragma unroll
    for (int k = 0; k < 64; k++) p[k] = g_pooled[t * 64 + k];

    float h[32];
#pragma unroll
    for (int j = 0; j < 32; j++) {
        float s = bc1[j];
#pragma unroll
        for (int k = 0; k < 64; k++) s += p[k] * W1s[k * 32 + j];
        h[j] = fmaxf(s, 0.0f);
    }
#pragma unroll
    for (int o = 0; o < 2; o++) {
        float s = bc2[o];
#pragma unroll
        for (int j = 0; j < 32; j++) s += h[j] * W2s[j * 2 + o];
        out[t * 2 + o] = s;
    }
}

// ---------------- launch ----------------
extern "C" void kernel_launch(void* const* d_in, const int* in_sizes, int n_in,
                              void* d_out, int out_size) {
    const float* x     = (const float*)d_in[0];
    const int*   ei    = (const int*)d_in[1];    // int32 (JAX x64 disabled)
    const int*   batch = (const int*)d_in[2];    // int32
    const float* W1  = (const float*)d_in[3];
    const float* b1  = (const float*)d_in[4];
    const float* W2  = (const float*)d_in[5];
    const float* b2  = (const float*)d_in[6];
    const float* W3  = (const float*)d_in[7];
    const float* b3  = (const float*)d_in[8];
    const float* Wc1 = (const float*)d_in[9];
    const float* bc1 = (const float*)d_in[10];
    const float* Wc2 = (const float*)d_in[11];
    const float* bc2 = (const float*)d_in[12];
    float* out = (float*)d_out;

    const int TB = 256;
    const int gN  = (N_NODES + TB - 1) / TB;
    const int gE  = (N_EDGES + TB - 1) / TB;
    const int gW  = (N_NODES * 32 + TB - 1) / TB;        // warp-per-node grid
    const int gG  = (N_NODES + GEMM_T - 1) / GEMM_T;     // gemm grid (128 thr)

    // CSR-by-dst preprocessing
    k_zero<<<gN, TB>>>();
    k_count<<<gE, TB>>>(ei + N_EDGES);
    k_scan1<<<SCAN_NB, SCAN_B>>>();     // block sums + dis
    k_scan2<<<1, 128>>>();              // scan block sums
    k_scan3<<<SCAN_NB, SCAN_B>>>();     // final offsets
    k_scatter<<<gE, TB>>>(ei);

    // layer 1
    k_gemm<IN_DIM, false, false><<<gG, GEMM_T>>>(x, W1);
    k_agg<<<gW, TB>>>(b1);
    // layer 2
    k_gemm<HID, true, true><<<gG, GEMM_T>>>(nullptr, W2);
    k_agg<<<gW, TB>>>(b2);
    // layer 3
    k_gemm<HID, true, true><<<gG, GEMM_T>>>(nullptr, W3);
    k_agg<<<gW, TB>>>(b3);

    // pool + classifier
    k_pool<<<N_GRAPHS, 256>>>(batch);
    k_cls<<<1, 64>>>(Wc1, bc1, Wc2, bc2, out);
}

// round 8
// speedup vs baseline: 1.5040x; 1.5040x over previous
#include <cuda_runtime.h>
#include <cuda_fp16.h>

#define N_NODES 100000
#define N_EDGES 1600000
#define IN_DIM  128
#define HID     64
#define N_GRAPHS 64

#define SCAN_B 1024
#define SCAN_NB ((N_NODES + SCAN_B - 1) / SCAN_B)   // 98

// ---------------- static device scratch (no allocations allowed) ----------------
__device__ int   g_cnt[N_NODES];
__device__ int   g_cur[N_NODES];
__device__ int   g_off[N_NODES + 1];
__device__ float g_dis[N_NODES];
__device__ int   g_bsum[SCAN_NB];
__device__ int   g_bpre[SCAN_NB];
__device__ __align__(16) int2   g_csr[N_EDGES];                    // (src, norm-bits)
__device__ __align__(16) __half g_Xh[(size_t)N_NODES * IN_DIM];    // fp16 input features
__device__ __align__(16) __half g_Ah[(size_t)N_NODES * HID];       // GEMM out (messages)
__device__ __align__(16) __half g_Bh[(size_t)N_NODES * HID];       // agg out (layer act)
__device__ __align__(16) unsigned g_Wp1[IN_DIM * 32];              // repacked W1 frags
__device__ __align__(16) unsigned g_Wp2[HID * 32];
__device__ __align__(16) unsigned g_Wp3[HID * 32];
__device__ float g_pooled[N_GRAPHS * HID];

// ---------------- preprocessing ----------------
__global__ __launch_bounds__(256) void k_zero() {
    int i = blockIdx.x * blockDim.x + threadIdx.x;
    if (i < N_NODES) { g_cnt[i] = 0; g_cur[i] = 0; }
}

__global__ __launch_bounds__(256) void k_count(const int* __restrict__ dst32) {
    int e = blockIdx.x * blockDim.x + threadIdx.x;
    if (e < N_EDGES) atomicAdd(&g_cnt[dst32[e]], 1);
}

__global__ __launch_bounds__(SCAN_B) void k_scan1() {
    int i = blockIdx.x * SCAN_B + threadIdx.x;
    int v = 0;
    if (i < N_NODES) {
        v = g_cnt[i];
        g_dis[i] = rsqrtf((float)(v + 1));
    }
    int lane = threadIdx.x & 31, wid = threadIdx.x >> 5;
    int s = v;
#pragma unroll
    for (int d = 16; d > 0; d >>= 1) s += __shfl_down_sync(~0u, s, d);
    __shared__ int wsum[32];
    if (lane == 0) wsum[wid] = s;
    __syncthreads();
    if (wid == 0) {
        int t = wsum[lane];
#pragma unroll
        for (int d = 16; d > 0; d >>= 1) t += __shfl_down_sync(~0u, t, d);
        if (lane == 0) g_bsum[blockIdx.x] = t;
    }
}

__global__ __launch_bounds__(128) void k_scan2() {
    __shared__ int sm[128];
    int t = threadIdx.x;
    int v = (t < SCAN_NB) ? g_bsum[t] : 0;
    sm[t] = v;
    __syncthreads();
    for (int d = 1; d < 128; d <<= 1) {
        int y = (t >= d) ? sm[t - d] : 0;
        __syncthreads();
        sm[t] += y;
        __syncthreads();
    }
    if (t < SCAN_NB) g_bpre[t] = sm[t] - v;
    if (t == 0) g_off[N_NODES] = N_EDGES;
}

__global__ __launch_bounds__(SCAN_B) void k_scan3() {
    int i = blockIdx.x * SCAN_B + threadIdx.x;
    int v = (i < N_NODES) ? g_cnt[i] : 0;
    int lane = threadIdx.x & 31, wid = threadIdx.x >> 5;
    int x = v;
#pragma unroll
    for (int d = 1; d < 32; d <<= 1) {
        int y = __shfl_up_sync(~0u, x, d);
        if (lane >= d) x += y;
    }
    __shared__ int wsum[32];
    if (lane == 31) wsum[wid] = x;
    __syncthreads();
    if (wid == 0) {
        int s = wsum[lane];
#pragma unroll
        for (int d = 1; d < 32; d <<= 1) {
            int y = __shfl_up_sync(~0u, s, d);
            if (lane >= d) s += y;
        }
        wsum[lane] = s;
    }
    __syncthreads();
    if (i < N_NODES)
        g_off[i] = (x - v) + (wid > 0 ? wsum[wid - 1] : 0) + g_bpre[blockIdx.x];
}

__global__ __launch_bounds__(256) void k_scatter(const int* __restrict__ ei) {
    int e = blockIdx.x * blockDim.x + threadIdx.x;
    if (e >= N_EDGES) return;
    int s = ei[e];
    int d = ei[N_EDGES + e];
    int pos = g_off[d] + atomicAdd(&g_cur[d], 1);
    float nrm = g_dis[s] * g_dis[d];
    g_csr[pos] = make_int2(s, __float_as_int(nrm));
}

// ---------------- conversions ----------------
__global__ __launch_bounds__(256) void k_xconv(const float* __restrict__ x) {
    int i = blockIdx.x * blockDim.x + threadIdx.x;       // one float4 -> one uint2
    const int total = N_NODES * IN_DIM / 4;
    if (i >= total) return;
    float4 v = ((const float4*)x)[i];
    __half2 h0 = __floats2half2_rn(v.x, v.y);
    __half2 h1 = __floats2half2_rn(v.z, v.w);
    uint2 pk;
    pk.x = *(unsigned*)&h0;
    pk.y = *(unsigned*)&h1;
    ((uint2*)g_Xh)[i] = pk;
}

// W fp32 [K,64] -> B-fragment-packed fp16 (m16n8k16 layout)
// idx = ((kt*8+nt)*32 + lane)*2 + r ; lane: t=lane&3, g=lane>>2
// k0 = kt*16 + 2t + 8r ; n = nt*8 + g ; value = half2(W[k0][n], W[k0+1][n])
__global__ __launch_bounds__(128) void k_wconv(const float* __restrict__ W,
                                               unsigned* __restrict__ Wp, int K) {
    int idx = blockIdx.x * blockDim.x + threadIdx.x;
    if (idx >= K * 32) return;
    int r    = idx & 1;
    int lane = (idx >> 1) & 31;
    int nt   = (idx >> 6) & 7;
    int kt   = idx >> 9;
    int t = lane & 3, g = lane >> 2;
    int k0 = kt * 16 + 2 * t + 8 * r;
    int n  = nt * 8 + g;
    __half2 h = __floats2half2_rn(W[k0 * 64 + n], W[(k0 + 1) * 64 + n]);
    Wp[idx] = *(unsigned*)&h;
}

// ---------------- tensor-core GEMM: g_Ah = act(Xh) @ W ----------------
// block = 128 thr (4 warps), 64 rows/block, each warp 16 rows x 64 cols.
template<int K, bool RELU>
__global__ __launch_bounds__(128) void k_gemm_mma(const __half* __restrict__ Xh,
                                                  const unsigned* __restrict__ Wp) {
    __shared__ uint2 Wps[(K / 16) * 8 * 32];
    const uint2* Wp2 = (const uint2*)Wp;
    for (int i = threadIdx.x; i < (K / 16) * 8 * 32; i += 128) Wps[i] = Wp2[i];
    __syncthreads();

    int warp = threadIdx.x >> 5, lane = threadIdx.x & 31;
    int g = lane >> 2, t = lane & 3;
    int row0 = blockIdx.x * 64 + warp * 16 + g;          // rows row0 and row0+8
    long rA = min(row0, N_NODES - 1);
    long rB = min(row0 + 8, N_NODES - 1);
    const __half* pa = Xh + rA * K + 2 * t;
    const __half* pb = Xh + rB * K + 2 * t;

    float acc[8][4];
#pragma unroll
    for (int nt = 0; nt < 8; nt++)
#pragma unroll
        for (int j = 0; j < 4; j++) acc[nt][j] = 0.0f;

    const __half2 zero2 = __float2half2_rn(0.0f);
#pragma unroll
    for (int kt = 0; kt < K / 16; kt++) {
        unsigned a0 = *(const unsigned*)(pa + kt * 16);
        unsigned a1 = *(const unsigned*)(pb + kt * 16);
        unsigned a2 = *(const unsigned*)(pa + kt * 16 + 8);
        unsigned a3 = *(const unsigned*)(pb + kt * 16 + 8);
        if (RELU) {
            __half2 v;
            v = __hmax2(*(__half2*)&a0, zero2); a0 = *(unsigned*)&v;
            v = __hmax2(*(__half2*)&a1, zero2); a1 = *(unsigned*)&v;
            v = __hmax2(*(__half2*)&a2, zero2); a2 = *(unsigned*)&v;
            v = __hmax2(*(__half2*)&a3, zero2); a3 = *(unsigned*)&v;
        }
#pragma unroll
        for (int nt = 0; nt < 8; nt++) {
            uint2 b = Wps[(kt * 8 + nt) * 32 + lane];
            asm volatile(
                "mma.sync.aligned.m16n8k16.row.col.f32.f16.f16.f32 "
                "{%0,%1,%2,%3}, {%4,%5,%6,%7}, {%8,%9}, {%0,%1,%2,%3};"
                : "+f"(acc[nt][0]), "+f"(acc[nt][1]), "+f"(acc[nt][2]), "+f"(acc[nt][3])
                : "r"(a0), "r"(a1), "r"(a2), "r"(a3), "r"(b.x), "r"(b.y));
        }
    }

    if (row0 < N_NODES) {
#pragma unroll
        for (int nt = 0; nt < 8; nt++) {
            __half2 h = __floats2half2_rn(acc[nt][0], acc[nt][1]);
            *(unsigned*)&g_Ah[(size_t)row0 * HID + nt * 8 + 2 * t] = *(unsigned*)&h;
        }
    }
    if (row0 + 8 < N_NODES) {
#pragma unroll
        for (int nt = 0; nt < 8; nt++) {
            __half2 h = __floats2half2_rn(acc[nt][2], acc[nt][3]);
            *(unsigned*)&g_Ah[(size_t)(row0 + 8) * HID + nt * 8 + 2 * t] = *(unsigned*)&h;
        }
    }
}

// ---------------- aggregation: one warp per dst node ----------------
__global__ __launch_bounds__(256) void k_agg(const float* __restrict__ bias) {
    int w = (blockIdx.x * blockDim.x + threadIdx.x) >> 5;
    if (w >= N_NODES) return;
    int lane = threadIdx.x & 31;

    const __half2* A2 = (const __half2*)g_Ah;
    float dis = g_dis[w];
    float2 b2 = ((const float2*)bias)[lane];
    float2 self = __half22float2(A2[(size_t)w * 32 + lane]);
    float sn = dis * dis;
    float ax = self.x * sn + b2.x;
    float ay = self.y * sn + b2.y;

    int p   = g_off[w];
    int end = g_off[w + 1];
    for (; p + 2 <= end; p += 2) {
        int2 e0 = g_csr[p];
        int2 e1 = g_csr[p + 1];
        float n0 = __int_as_float(e0.y);
        float n1 = __int_as_float(e1.y);
        float2 v0 = __half22float2(A2[(size_t)e0.x * 32 + lane]);
        float2 v1 = __half22float2(A2[(size_t)e1.x * 32 + lane]);
        ax += v0.x * n0; ay += v0.y * n0;
        ax += v1.x * n1; ay += v1.y * n1;
    }
    if (p < end) {
        int2 e0 = g_csr[p];
        float n0 = __int_as_float(e0.y);
        float2 v0 = __half22float2(A2[(size_t)e0.x * 32 + lane]);
        ax += v0.x * n0; ay += v0.y * n0;
    }

    ((__half2*)g_Bh)[(size_t)w * 32 + lane] = __floats2half2_rn(ax, ay);
}

// ---------------- global mean pool (batch is sorted int32) ----------------
__device__ __forceinline__ int lb_i32(const int* a, int n, int v) {
    int lo = 0, hi = n;
    while (lo < hi) {
        int mid = (lo + hi) >> 1;
        if (a[mid] < v) lo = mid + 1; else hi = mid;
    }
    return lo;
}

__global__ __launch_bounds__(256) void k_pool(const int* __restrict__ batch) {
    int g = blockIdx.x;
    int lo = lb_i32(batch, N_NODES, g);
    int hi = lb_i32(batch, N_NODES, g + 1);
    int c2 = threadIdx.x & 31;          // half2 column (2 cols per thread)
    int sub = threadIdx.x >> 5;         // 0..7
    const __half2* B2 = (const __half2*)g_Bh;
    float sx = 0.0f, sy = 0.0f;
    for (int i = lo + sub; i < hi; i += 8) {
        float2 v = __half22float2(B2[(size_t)i * 32 + c2]);
        sx += v.x; sy += v.y;
    }
    __shared__ float redx[256], redy[256];
    redx[threadIdx.x] = sx;
    redy[threadIdx.x] = sy;
    __syncthreads();
    if (sub == 0) {
        float tx = 0.0f, ty = 0.0f;
#pragma unroll
        for (int q = 0; q < 8; q++) { tx += redx[q * 32 + c2]; ty += redy[q * 32 + c2]; }
        float inv = 1.0f / fmaxf((float)(hi - lo), 1.0f);
        g_pooled[g * HID + 2 * c2]     = tx * inv;
        g_pooled[g * HID + 2 * c2 + 1] = ty * inv;
    }
}

// ---------------- classifier MLP ----------------
__global__ __launch_bounds__(64) void k_cls(const float* __restrict__ Wc1,
                                            const float* __restrict__ bc1,
                                            const float* __restrict__ Wc2,
                                            const float* __restrict__ bc2,
                                            float* __restrict__ out) {
    __shared__ float W1s[64 * 32];
    __shared__ float W2s[32 * 2];
    int t = threadIdx.x;
    for (int i = t; i < 64 * 32; i += 64) W1s[i] = Wc1[i];
    if (t < 64) W2s[t] = Wc2[t];
    __syncthreads();

    float p[64];
#pragma unroll
    for (int k = 0; k < 64; k++) p[k] = g_pooled[t * 64 + k];

    float h[32];
#pragma unroll
    for (int j = 0; j < 32; j++) {
        float s = bc1[j];
#pragma unroll
        for (int k = 0; k < 64; k++) s += p[k] * W1s[k * 32 + j];
        h[j] = fmaxf(s, 0.0f);
    }
#pragma unroll
    for (int o = 0; o < 2; o++) {
        float s = bc2[o];
#pragma unroll
        for (int j = 0; j < 32; j++) s += h[j] * W2s[j * 2 + o];
        out[t * 2 + o] = s;
    }
}

// ---------------- launch ----------------
extern "C" void kernel_launch(void* const* d_in, const int* in_sizes, int n_in,
                              void* d_out, int out_size) {
    const float* x     = (const float*)d_in[0];
    const int*   ei    = (const int*)d_in[1];
    const int*   batch = (const int*)d_in[2];
    const float* W1  = (const float*)d_in[3];
    const float* b1  = (const float*)d_in[4];
    const float* W2  = (const float*)d_in[5];
    const float* b2  = (const float*)d_in[6];
    const float* W3  = (const float*)d_in[7];
    const float* b3  = (const float*)d_in[8];
    const float* Wc1 = (const float*)d_in[9];
    const float* bc1 = (const float*)d_in[10];
    const float* Wc2 = (const float*)d_in[11];
    const float* bc2 = (const float*)d_in[12];
    float* out = (float*)d_out;

    const int TB = 256;
    const int gN  = (N_NODES + TB - 1) / TB;
    const int gE  = (N_EDGES + TB - 1) / TB;
    const int gW  = (N_NODES * 32 + TB - 1) / TB;
    const int gM  = (N_NODES + 63) / 64;                     // mma gemm grid
    const int gX  = (N_NODES * IN_DIM / 4 + TB - 1) / TB;

    // DEVICE addresses of __device__ globals (host symbol is NOT the device ptr!)
    unsigned *wp1, *wp2, *wp3;
    __half *xh, *bh;
    cudaGetSymbolAddress((void**)&wp1, g_Wp1);
    cudaGetSymbolAddress((void**)&wp2, g_Wp2);
    cudaGetSymbolAddress((void**)&wp3, g_Wp3);
    cudaGetSymbolAddress((void**)&xh,  g_Xh);
    cudaGetSymbolAddress((void**)&bh,  g_Bh);

    // conversions
    k_xconv<<<gX, TB>>>(x);
    k_wconv<<<(IN_DIM * 32 + 127) / 128, 128>>>(W1, wp1, IN_DIM);
    k_wconv<<<(HID * 32 + 127) / 128, 128>>>(W2, wp2, HID);
    k_wconv<<<(HID * 32 + 127) / 128, 128>>>(W3, wp3, HID);

    // CSR-by-dst preprocessing
    k_zero<<<gN, TB>>>();
    k_count<<<gE, TB>>>(ei + N_EDGES);
    k_scan1<<<SCAN_NB, SCAN_B>>>();
    k_scan2<<<1, 128>>>();
    k_scan3<<<SCAN_NB, SCAN_B>>>();
    k_scatter<<<gE, TB>>>(ei);

    // layer 1
    k_gemm_mma<IN_DIM, false><<<gM, 128>>>(xh, wp1);
    k_agg<<<gW, TB>>>(b1);
    // layer 2
    k_gemm_mma<HID, true><<<gM, 128>>>(bh, wp2);
    k_agg<<<gW, TB>>>(b2);
    // layer 3
    k_gemm_mma<HID, true><<<gM, 128>>>(bh, wp3);
    k_agg<<<gW, TB>>>(b3);

    // pool + classifier
    k_pool<<<N_GRAPHS, 256>>>(batch);
    k_cls<<<1, 64>>>(Wc1, bc1, Wc2, bc2, out);
}